// round 12
// baseline (speedup 1.0000x reference)
#include <cuda_runtime.h>
#include <cuda_fp16.h>

#define NN 100000
#define NE 1600000
#define NG 1000
#define F1 64
#define F2 128
#define SCAN_B 1024
#define NB_SCAN ((NN + SCAN_B - 1) / SCAN_B)   // 98
#define NPB 80          // nodes per block in l2pool (100000/80 = 1250 exact)

// Scratch (device globals — no allocation allowed)
__device__ int   d_hist[NN];
__device__ int   d_row[NN];
__device__ int   d_cur[NN];
__device__ int   d_bsum[NB_SCAN];
__device__ int   d_csr[NE];
__device__ float d_dinv[NN];
__device__ __align__(16) __half2 d_p0h[NN * 4];          // fp16 dinv*x, 16B/node (6 used)
__device__ __align__(16) __half2 d_p1h[NN * (F1 / 2)];   // fp16 L1 messages, 128B/node
__device__ __align__(16) __half2 d_acc1h[NN * (F1 / 2)]; // fp16 aggregated L1, 128B/node
__device__ __align__(16) float   d_pool[NG * F2];
__device__ float d_cntf[NG];

__device__ __forceinline__ float relu(float v) { return v > 0.f ? v : 0.f; }

// ---------------------------------------------------------------------------
// 0) Zero hist / pool / cnt
// ---------------------------------------------------------------------------
__global__ void k_init() {
    int i = blockIdx.x * blockDim.x + threadIdx.x;
    if (i < NN)      d_hist[i] = 0;
    if (i < NG * F2) d_pool[i] = 0.f;
    if (i < NG)      d_cntf[i] = 0.f;
}

// ---------------------------------------------------------------------------
// 1) Histogram of dst (in-degree); 4 edges/thread via int4
// ---------------------------------------------------------------------------
__global__ void k_hist(const int* __restrict__ ei) {
    int i = blockIdx.x * blockDim.x + threadIdx.x;
    if (i * 4 >= NE) return;
    int4 d4 = *reinterpret_cast<const int4*>(&ei[NE + i * 4]);
    atomicAdd(&d_hist[d4.x], 1);
    atomicAdd(&d_hist[d4.y], 1);
    atomicAdd(&d_hist[d4.z], 1);
    atomicAdd(&d_hist[d4.w], 1);
}

// ---------------------------------------------------------------------------
// 2) Per-block exclusive scan of hist -> row (pre-offset) + block sums,
//    FUSED with dinv/p0h/cnt generation.
// ---------------------------------------------------------------------------
__global__ void k_scan1(const float* __restrict__ x, const int* __restrict__ batch) {
    __shared__ int wsum[32];
    int tid  = threadIdx.x;              // 1024
    int lane = tid & 31, w = tid >> 5;
    int i = blockIdx.x * SCAN_B + tid;
    bool ok = (i < NN);
    int v = ok ? d_hist[i] : 0;

    // independent work early: dinv + x loads (overlap scan latency)
    float dv = rsqrtf((float)v + 1.f);   // +1 self loop
    float2 x0, x1, x2;
    if (ok) {
        const float2* xp = reinterpret_cast<const float2*>(x) + i * 3;
        x0 = xp[0]; x1 = xp[1]; x2 = xp[2];
    }

    int incl = v;
#pragma unroll
    for (int off = 1; off < 32; off <<= 1) {
        int t = __shfl_up_sync(0xffffffffu, incl, off);
        if (lane >= off) incl += t;
    }
    if (lane == 31) wsum[w] = incl;
    __syncthreads();
    if (w == 0) {
        int s = wsum[lane];
        int si = s;
#pragma unroll
        for (int off = 1; off < 32; off <<= 1) {
            int t = __shfl_up_sync(0xffffffffu, si, off);
            if (lane >= off) si += t;
        }
        wsum[lane] = si - s;             // exclusive warp offsets
    }
    __syncthreads();
    int woff = wsum[w];
    if (tid == SCAN_B - 1) d_bsum[blockIdx.x] = woff + incl;
    if (!ok) return;
    d_row[i] = incl - v + woff;          // pre-block-offset exclusive scan

    d_dinv[i] = dv;
    __half2 h0 = __floats2half2_rn(dv * x0.x, dv * x0.y);
    __half2 h1 = __floats2half2_rn(dv * x1.x, dv * x1.y);
    __half2 h2 = __floats2half2_rn(dv * x2.x, dv * x2.y);
    __half2 h3 = __floats2half2_rn(0.f, 0.f);
    uint4 pk = make_uint4(*reinterpret_cast<unsigned*>(&h0),
                          *reinterpret_cast<unsigned*>(&h1),
                          *reinterpret_cast<unsigned*>(&h2),
                          *reinterpret_cast<unsigned*>(&h3));
    *reinterpret_cast<uint4*>(&d_p0h[i * 4]) = pk;
    atomicAdd(&d_cntf[batch[i]], 1.f);
}

// ---------------------------------------------------------------------------
// 3) Row fixup: redundant shfl-scan of 98 block sums; row += soff; cur = row
// ---------------------------------------------------------------------------
__global__ void k_scan3() {
    __shared__ int wsum4[4];
    __shared__ int soff[128];
    int tid = threadIdx.x;               // 256
    int incl = 0, v = 0;
    if (tid < 128) {
        v = (tid < NB_SCAN) ? d_bsum[tid] : 0;
        incl = v;
        int lane = tid & 31;
#pragma unroll
        for (int off = 1; off < 32; off <<= 1) {
            int t = __shfl_up_sync(0xffffffffu, incl, off);
            if (lane >= off) incl += t;
        }
        if (lane == 31) wsum4[tid >> 5] = incl;
    }
    __syncthreads();
    if (tid < 128) {
        int w = tid >> 5;
        int add = 0;
#pragma unroll
        for (int k = 0; k < 4; k++) add += (k < w) ? wsum4[k] : 0;
        soff[tid] = incl - v + add;
    }
    __syncthreads();
    int n = blockIdx.x * blockDim.x + tid;
    if (n >= NN) return;
    int r = d_row[n] + soff[n >> 10];
    d_row[n] = r;
    d_cur[n] = r;
}

// ---------------------------------------------------------------------------
// 4) CSR fill: csr[pos] = src, grouped by dst; 4 edges/thread via int4
// ---------------------------------------------------------------------------
__global__ void k_fill(const int* __restrict__ ei) {
    int i = blockIdx.x * blockDim.x + threadIdx.x;
    if (i * 4 >= NE) return;
    int4 s4 = *reinterpret_cast<const int4*>(&ei[i * 4]);
    int4 d4 = *reinterpret_cast<const int4*>(&ei[NE + i * 4]);
    d_csr[atomicAdd(&d_cur[d4.x], 1)] = s4.x;
    d_csr[atomicAdd(&d_cur[d4.y], 1)] = s4.y;
    d_csr[atomicAdd(&d_cur[d4.z], 1)] = s4.z;
    d_csr[atomicAdd(&d_cur[d4.w], 1)] = s4.w;
}

// ---------------------------------------------------------------------------
// 5) Fused PULL0 + L1.  p0 rows are 16B fp16 -> ONE 16B load per edge,
//    unroll-by-4 for MLP; accumulate fp32; then t@W1, relu, store fp16 p1.
// ---------------------------------------------------------------------------
__device__ __forceinline__ void acc_u4(float2& a0, float2& a1, float2& a2, uint4 v) {
    float2 f0 = __half22float2(*reinterpret_cast<__half2*>(&v.x));
    float2 f1 = __half22float2(*reinterpret_cast<__half2*>(&v.y));
    float2 f2 = __half22float2(*reinterpret_cast<__half2*>(&v.z));
    a0.x += f0.x; a0.y += f0.y;
    a1.x += f1.x; a1.y += f1.y;
    a2.x += f2.x; a2.y += f2.y;
}

__global__ void k_pull0l1(const float* __restrict__ W1, const float* __restrict__ b1) {
    __shared__ float w[6 * F1];
    __shared__ float bs[F1];
    for (int j = threadIdx.x; j < 6 * F1; j += blockDim.x) w[j] = W1[j];
    if (threadIdx.x < F1) bs[threadIdx.x] = b1[threadIdx.x];
    __syncthreads();
    int n = blockIdx.x * blockDim.x + threadIdx.x;
    if (n >= NN) return;
    int start = d_row[n];
    int deg   = d_hist[n];
    const uint4* P = reinterpret_cast<const uint4*>(d_p0h);
    float2 a0 = {0.f, 0.f}, a1 = {0.f, 0.f}, a2 = {0.f, 0.f};
    acc_u4(a0, a1, a2, P[n]);            // self loop
    int j = 0;
    for (; j + 4 <= deg; j += 4) {
        int s0 = d_csr[start + j];
        int s1 = d_csr[start + j + 1];
        int s2 = d_csr[start + j + 2];
        int s3 = d_csr[start + j + 3];
        uint4 v0 = P[s0];
        uint4 v1 = P[s1];
        uint4 v2 = P[s2];
        uint4 v3 = P[s3];
        acc_u4(a0, a1, a2, v0);
        acc_u4(a0, a1, a2, v1);
        acc_u4(a0, a1, a2, v2);
        acc_u4(a0, a1, a2, v3);
    }
    for (; j < deg; j++) acc_u4(a0, a1, a2, P[d_csr[start + j]]);
    float t[6] = {a0.x, a0.y, a1.x, a1.y, a2.x, a2.y};
    float dv = d_dinv[n];
#pragma unroll
    for (int jj = 0; jj < 16; jj++) {    // 4 feats per iter -> 2 half2 (8B store)
        float o[4];
#pragma unroll
        for (int c = 0; c < 4; c++) {
            int idx = jj * 4 + c;
            float acc = 0.f;
#pragma unroll
            for (int k = 0; k < 6; k++) acc += t[k] * w[k * F1 + idx];
            o[c] = dv * relu(dv * acc + bs[idx]);
        }
        __half2 h0 = __floats2half2_rn(o[0], o[1]);
        __half2 h1 = __floats2half2_rn(o[2], o[3]);
        __half2* dst = &d_p1h[n * (F1 / 2) + jj * 2];
        *reinterpret_cast<uint2*>(dst) = make_uint2(
            *reinterpret_cast<unsigned*>(&h0), *reinterpret_cast<unsigned*>(&h1));
    }
}

// ---------------------------------------------------------------------------
// 6) PULL layer 1: acc1[n] = p1[n] + sum_in p1[s].  Warp per node,
//    one half2 per lane (128B line per edge), fp32 accumulate, fp16 store.
// ---------------------------------------------------------------------------
__global__ void k_pull1() {
    int wid  = (blockIdx.x * blockDim.x + threadIdx.x) >> 5;
    int lane = threadIdx.x & 31;
    if (wid >= NN) return;
    int n = wid;
    int start = d_row[n];
    int deg   = d_hist[n];
    const __half2* p = d_p1h;
    float2 acc = __half22float2(p[n * 32 + lane]);
    int j = 0;
    for (; j + 4 <= deg; j += 4) {
        int s0 = d_csr[start + j];
        int s1 = d_csr[start + j + 1];
        int s2 = d_csr[start + j + 2];
        int s3 = d_csr[start + j + 3];
        float2 u0 = __half22float2(p[s0 * 32 + lane]);
        float2 u1 = __half22float2(p[s1 * 32 + lane]);
        float2 u2 = __half22float2(p[s2 * 32 + lane]);
        float2 u3 = __half22float2(p[s3 * 32 + lane]);
        acc.x += (u0.x + u1.x) + (u2.x + u3.x);
        acc.y += (u0.y + u1.y) + (u2.y + u3.y);
    }
    for (; j < deg; j++) {
        int s0 = d_csr[start + j];
        float2 u = __half22float2(p[s0 * 32 + lane]);
        acc.x += u.x;
        acc.y += u.y;
    }
    d_acc1h[n * 32 + lane] = __floats2half2_rn(acc.x, acc.y);
}

// ---------------------------------------------------------------------------
// 7) out2 = relu(dinv*(acc1@W2) + b2), pooled.  acc1 read as fp16, converted
//    to fp32 node-pair float2 in smem; inner loop = LDS.128 + 2 FFMA2.
// ---------------------------------------------------------------------------
__global__ void k_l2pool(const float* __restrict__ W2, const float* __restrict__ b2,
                         const int* __restrict__ batch) {
    __shared__ float2 inp[NPB / 2][F1];   // 20 KB
    __shared__ float dv_s[NPB];
    __shared__ int   bt_s[NPB];
    int tid = threadIdx.x;                // output feature 0..127
    unsigned long long wp[F1];
#pragma unroll
    for (int k = 0; k < F1; k++) {
        float wv = W2[k * F2 + tid];
        asm("mov.b64 %0, {%1, %1};" : "=l"(wp[k]) : "f"(wv));
    }
    float bb = b2[tid];
    int base = blockIdx.x * NPB;
    for (int i = tid; i < NPB * 32; i += 128) {
        int nl = i >> 5;                  // local node
        int hk = i & 31;                  // half2 index -> feats 2hk, 2hk+1
        float2 f = __half22float2(d_acc1h[(base + nl) * 32 + hk]);
        reinterpret_cast<float*>(&inp[nl >> 1][2 * hk + 0])[nl & 1] = f.x;
        reinterpret_cast<float*>(&inp[nl >> 1][2 * hk + 1])[nl & 1] = f.y;
    }
    if (tid < NPB) {
        dv_s[tid] = d_dinv[base + tid];
        bt_s[tid] = batch[base + tid];
    }
    __syncthreads();
    float pacc = 0.f;
    int cgid = bt_s[0];
    for (int p = 0; p < NPB / 2; p++) {
        unsigned long long acc = 0ull;    // (0.f, 0.f)
        const ulonglong2* ip = reinterpret_cast<const ulonglong2*>(&inp[p][0]);
#pragma unroll
        for (int k = 0; k < F1; k += 2) {
            ulonglong2 pv = ip[k >> 1];   // LDS.128: two packed k's
            asm("fma.rn.f32x2 %0, %1, %2, %3;" : "=l"(acc) : "l"(wp[k]),     "l"(pv.x), "l"(acc));
            asm("fma.rn.f32x2 %0, %1, %2, %3;" : "=l"(acc) : "l"(wp[k + 1]), "l"(pv.y), "l"(acc));
        }
        float a0, a1;
        asm("mov.b64 {%0, %1}, %2;" : "=f"(a0), "=f"(a1) : "l"(acc));
        int n0 = 2 * p, n1 = 2 * p + 1;
        int g0 = bt_s[n0];
        if (g0 != cgid) { atomicAdd(&d_pool[cgid * F2 + tid], pacc); pacc = 0.f; cgid = g0; }
        pacc += relu(dv_s[n0] * a0 + bb);
        int g1 = bt_s[n1];
        if (g1 != cgid) { atomicAdd(&d_pool[cgid * F2 + tid], pacc); pacc = 0.f; cgid = g1; }
        pacc += relu(dv_s[n1] * a1 + bb);
    }
    atomicAdd(&d_pool[cgid * F2 + tid], pacc);
}

// ---------------------------------------------------------------------------
// 8) out[g] = (pool[g]/max(cnt,1)) @ Wfc + bfc      [1000, 2]
// ---------------------------------------------------------------------------
__global__ void k_fc(const float* __restrict__ Wfc, const float* __restrict__ bfc,
                     float* __restrict__ out) {
    int i = blockIdx.x * blockDim.x + threadIdx.x;
    if (i >= NG * 2) return;
    int g = i >> 1;
    int o = i & 1;
    float cnt = d_cntf[g];
    float inv = 1.f / (cnt > 1.f ? cnt : 1.f);
    float a = 0.f;
#pragma unroll 8
    for (int k = 0; k < F2; k++) a += d_pool[g * F2 + k] * Wfc[k * 2 + o];
    out[i] = a * inv + bfc[o];
}

// ---------------------------------------------------------------------------
extern "C" void kernel_launch(void* const* d_in, const int* in_sizes, int n_in,
                              void* d_out, int out_size) {
    const float* x   = (const float*)d_in[0];
    const int*   ei  = (const int*)d_in[1];   // int32 (JAX x64 disabled)
    const int*   bat = (const int*)d_in[2];   // int32
    const float* W1  = (const float*)d_in[3];
    const float* b1  = (const float*)d_in[4];
    const float* W2  = (const float*)d_in[5];
    const float* b2  = (const float*)d_in[6];
    const float* Wfc = (const float*)d_in[7];
    const float* bfc = (const float*)d_in[8];
    float*       out = (float*)d_out;

    k_init   <<<(NG * F2 + 255) / 256, 256>>>();
    k_hist   <<<(NE / 4 + 255) / 256, 256>>>(ei);
    k_scan1  <<<NB_SCAN, SCAN_B>>>(x, bat);
    k_scan3  <<<(NN + 255) / 256, 256>>>();
    k_fill   <<<(NE / 4 + 255) / 256, 256>>>(ei);
    k_pull0l1<<<(NN + 255) / 256, 256>>>(W1, b1);
    k_pull1  <<<(NN * 32 + 255) / 256, 256>>>();
    k_l2pool <<<NN / NPB, 128>>>(W2, b2, bat);
    k_fc     <<<(NG * 2 + 255) / 256, 256>>>(Wfc, bfc, out);
}

// round 13
// speedup vs baseline: 1.1881x; 1.1881x over previous
#include <cuda_runtime.h>
#include <cuda_fp16.h>
#include <mma.h>

using namespace nvcuda;

#define NN 100000
#define NE 1600000
#define NG 1000
#define F1 64
#define F2 128
#define SCAN_B 1024
#define NB_SCAN ((NN + SCAN_B - 1) / SCAN_B)   // 98
#define NPB 80          // nodes per block in l2pool (100000/80 = 1250 exact)

// Scratch (device globals — no allocation allowed)
__device__ int   d_hist[NN];
__device__ int   d_row[NN];      // pre-block-offset exclusive scan
__device__ int   d_cur[NN];      // fill cursors (same basis as d_row)
__device__ int   d_bsum[NB_SCAN];
__device__ int   d_soff[128];    // scanned block sums (exclusive)
__device__ int   d_csr[NE];
__device__ float d_dinv[NN];
__device__ __align__(16) __half2 d_p0h[NN * 4];          // fp16 dinv*x, 16B/node (6 used)
__device__ __align__(16) __half2 d_p1h[NN * (F1 / 2)];   // fp16 L1 messages, 128B/node
__device__ __align__(16) __half2 d_acc1h[NN * (F1 / 2)]; // fp16 aggregated L1, 128B/node
__device__ __align__(16) float   d_pool[NG * F2];
__device__ float d_cntf[NG];

__device__ __forceinline__ float relu(float v) { return v > 0.f ? v : 0.f; }

// ---------------------------------------------------------------------------
// 0) Zero hist / pool / cnt
// ---------------------------------------------------------------------------
__global__ void k_init() {
    int i = blockIdx.x * blockDim.x + threadIdx.x;
    if (i < NN)      d_hist[i] = 0;
    if (i < NG * F2) d_pool[i] = 0.f;
    if (i < NG)      d_cntf[i] = 0.f;
}

// ---------------------------------------------------------------------------
// 1) Histogram of dst (in-degree); 4 edges/thread via int4
// ---------------------------------------------------------------------------
__global__ void k_hist(const int* __restrict__ ei) {
    int i = blockIdx.x * blockDim.x + threadIdx.x;
    if (i * 4 >= NE) return;
    int4 d4 = *reinterpret_cast<const int4*>(&ei[NE + i * 4]);
    atomicAdd(&d_hist[d4.x], 1);
    atomicAdd(&d_hist[d4.y], 1);
    atomicAdd(&d_hist[d4.z], 1);
    atomicAdd(&d_hist[d4.w], 1);
}

// ---------------------------------------------------------------------------
// 2) Per-block exclusive scan of hist -> row & cur (pre-offset) + block sums,
//    FUSED with dinv/p0h/cnt generation.
// ---------------------------------------------------------------------------
__global__ void k_scan1(const float* __restrict__ x, const int* __restrict__ batch) {
    __shared__ int wsum[32];
    int tid  = threadIdx.x;              // 1024
    int lane = tid & 31, w = tid >> 5;
    int i = blockIdx.x * SCAN_B + tid;
    bool ok = (i < NN);
    int v = ok ? d_hist[i] : 0;

    // independent work early: dinv + x loads (overlap scan latency)
    float dv = rsqrtf((float)v + 1.f);   // +1 self loop
    float2 x0, x1, x2;
    if (ok) {
        const float2* xp = reinterpret_cast<const float2*>(x) + i * 3;
        x0 = xp[0]; x1 = xp[1]; x2 = xp[2];
    }

    int incl = v;
#pragma unroll
    for (int off = 1; off < 32; off <<= 1) {
        int t = __shfl_up_sync(0xffffffffu, incl, off);
        if (lane >= off) incl += t;
    }
    if (lane == 31) wsum[w] = incl;
    __syncthreads();
    if (w == 0) {
        int s = wsum[lane];
        int si = s;
#pragma unroll
        for (int off = 1; off < 32; off <<= 1) {
            int t = __shfl_up_sync(0xffffffffu, si, off);
            if (lane >= off) si += t;
        }
        wsum[lane] = si - s;             // exclusive warp offsets
    }
    __syncthreads();
    int woff = wsum[w];
    if (tid == SCAN_B - 1) d_bsum[blockIdx.x] = woff + incl;
    if (!ok) return;
    int r = incl - v + woff;             // pre-block-offset exclusive scan
    d_row[i] = r;
    d_cur[i] = r;

    d_dinv[i] = dv;
    __half2 h0 = __floats2half2_rn(dv * x0.x, dv * x0.y);
    __half2 h1 = __floats2half2_rn(dv * x1.x, dv * x1.y);
    __half2 h2 = __floats2half2_rn(dv * x2.x, dv * x2.y);
    __half2 h3 = __floats2half2_rn(0.f, 0.f);
    uint4 pk = make_uint4(*reinterpret_cast<unsigned*>(&h0),
                          *reinterpret_cast<unsigned*>(&h1),
                          *reinterpret_cast<unsigned*>(&h2),
                          *reinterpret_cast<unsigned*>(&h3));
    *reinterpret_cast<uint4*>(&d_p0h[i * 4]) = pk;
    atomicAdd(&d_cntf[batch[i]], 1.f);
}

// ---------------------------------------------------------------------------
// 3) Tiny: exclusive shfl-scan of the 98 block sums -> d_soff.  One block.
// ---------------------------------------------------------------------------
__global__ void k_scan3() {
    __shared__ int wsum4[4];
    int tid = threadIdx.x;               // 128
    int v = (tid < NB_SCAN) ? d_bsum[tid] : 0;
    int incl = v;
    int lane = tid & 31;
#pragma unroll
    for (int off = 1; off < 32; off <<= 1) {
        int t = __shfl_up_sync(0xffffffffu, incl, off);
        if (lane >= off) incl += t;
    }
    if (lane == 31) wsum4[tid >> 5] = incl;
    __syncthreads();
    int w = tid >> 5;
    int add = 0;
#pragma unroll
    for (int k = 0; k < 4; k++) add += (k < w) ? wsum4[k] : 0;
    d_soff[tid] = incl - v + add;        // exclusive
}

// ---------------------------------------------------------------------------
// 4) CSR fill: csr[cur[d]++ + soff[d>>10]] = src; 4 edges/thread via int4
// ---------------------------------------------------------------------------
__global__ void k_fill(const int* __restrict__ ei) {
    int i = blockIdx.x * blockDim.x + threadIdx.x;
    if (i * 4 >= NE) return;
    int4 s4 = *reinterpret_cast<const int4*>(&ei[i * 4]);
    int4 d4 = *reinterpret_cast<const int4*>(&ei[NE + i * 4]);
    d_csr[atomicAdd(&d_cur[d4.x], 1) + d_soff[d4.x >> 10]] = s4.x;
    d_csr[atomicAdd(&d_cur[d4.y], 1) + d_soff[d4.y >> 10]] = s4.y;
    d_csr[atomicAdd(&d_cur[d4.z], 1) + d_soff[d4.z >> 10]] = s4.z;
    d_csr[atomicAdd(&d_cur[d4.w], 1) + d_soff[d4.w >> 10]] = s4.w;
}

// ---------------------------------------------------------------------------
// 5) Fused PULL0 + L1.  p0 rows are 16B fp16 -> ONE 16B load per edge,
//    unroll-by-4 for MLP; accumulate fp32; then t@W1, relu, store fp16 p1.
// ---------------------------------------------------------------------------
__device__ __forceinline__ void acc_u4(float2& a0, float2& a1, float2& a2, uint4 v) {
    float2 f0 = __half22float2(*reinterpret_cast<__half2*>(&v.x));
    float2 f1 = __half22float2(*reinterpret_cast<__half2*>(&v.y));
    float2 f2 = __half22float2(*reinterpret_cast<__half2*>(&v.z));
    a0.x += f0.x; a0.y += f0.y;
    a1.x += f1.x; a1.y += f1.y;
    a2.x += f2.x; a2.y += f2.y;
}

__global__ void k_pull0l1(const float* __restrict__ W1, const float* __restrict__ b1) {
    __shared__ float w[6 * F1];
    __shared__ float bs[F1];
    for (int j = threadIdx.x; j < 6 * F1; j += blockDim.x) w[j] = W1[j];
    if (threadIdx.x < F1) bs[threadIdx.x] = b1[threadIdx.x];
    __syncthreads();
    int n = blockIdx.x * blockDim.x + threadIdx.x;
    if (n >= NN) return;
    int start = d_row[n] + d_soff[n >> 10];
    int deg   = d_hist[n];
    const uint4* P = reinterpret_cast<const uint4*>(d_p0h);
    float2 a0 = {0.f, 0.f}, a1 = {0.f, 0.f}, a2 = {0.f, 0.f};
    acc_u4(a0, a1, a2, P[n]);            // self loop
    int j = 0;
    for (; j + 4 <= deg; j += 4) {
        int s0 = d_csr[start + j];
        int s1 = d_csr[start + j + 1];
        int s2 = d_csr[start + j + 2];
        int s3 = d_csr[start + j + 3];
        uint4 v0 = P[s0];
        uint4 v1 = P[s1];
        uint4 v2 = P[s2];
        uint4 v3 = P[s3];
        acc_u4(a0, a1, a2, v0);
        acc_u4(a0, a1, a2, v1);
        acc_u4(a0, a1, a2, v2);
        acc_u4(a0, a1, a2, v3);
    }
    for (; j < deg; j++) acc_u4(a0, a1, a2, P[d_csr[start + j]]);
    float t[6] = {a0.x, a0.y, a1.x, a1.y, a2.x, a2.y};
    float dv = d_dinv[n];
#pragma unroll
    for (int jj = 0; jj < 16; jj++) {    // 4 feats per iter -> 2 half2 (8B store)
        float o[4];
#pragma unroll
        for (int c = 0; c < 4; c++) {
            int idx = jj * 4 + c;
            float acc = 0.f;
#pragma unroll
            for (int k = 0; k < 6; k++) acc += t[k] * w[k * F1 + idx];
            o[c] = dv * relu(dv * acc + bs[idx]);
        }
        __half2 h0 = __floats2half2_rn(o[0], o[1]);
        __half2 h1 = __floats2half2_rn(o[2], o[3]);
        __half2* dst = &d_p1h[n * (F1 / 2) + jj * 2];
        *reinterpret_cast<uint2*>(dst) = make_uint2(
            *reinterpret_cast<unsigned*>(&h0), *reinterpret_cast<unsigned*>(&h1));
    }
}

// ---------------------------------------------------------------------------
// 6) PULL layer 1: acc1[n] = p1[n] + sum_in p1[s].  Warp per node,
//    one half2 per lane (128B line per edge), fp32 accumulate, fp16 store.
// ---------------------------------------------------------------------------
__global__ void k_pull1() {
    int wid  = (blockIdx.x * blockDim.x + threadIdx.x) >> 5;
    int lane = threadIdx.x & 31;
    if (wid >= NN) return;
    int n = wid;
    int start = d_row[n] + d_soff[n >> 10];
    int deg   = d_hist[n];
    const __half2* p = d_p1h;
    float2 acc = __half22float2(p[n * 32 + lane]);
    int j = 0;
    for (; j + 4 <= deg; j += 4) {
        int s0 = d_csr[start + j];
        int s1 = d_csr[start + j + 1];
        int s2 = d_csr[start + j + 2];
        int s3 = d_csr[start + j + 3];
        float2 u0 = __half22float2(p[s0 * 32 + lane]);
        float2 u1 = __half22float2(p[s1 * 32 + lane]);
        float2 u2 = __half22float2(p[s2 * 32 + lane]);
        float2 u3 = __half22float2(p[s3 * 32 + lane]);
        acc.x += (u0.x + u1.x) + (u2.x + u3.x);
        acc.y += (u0.y + u1.y) + (u2.y + u3.y);
    }
    for (; j < deg; j++) {
        int s0 = d_csr[start + j];
        float2 u = __half22float2(p[s0 * 32 + lane]);
        acc.x += u.x;
        acc.y += u.y;
    }
    d_acc1h[n * 32 + lane] = __floats2half2_rn(acc.x, acc.y);
}

// ---------------------------------------------------------------------------
// 7) out2 = relu(dinv*(acc1@W2) + b2), pooled.  TENSOR-CORE path:
//    wmma m16n16k16, A = acc1h (fp16, row-major gmem, ldm=64),
//    B = W2 fp16 in smem (row-major, ldm=128), C fp32.  4 warps split N=128;
//    B-fragments hoisted (loop-invariant).  Epilogue keeps the ordered
//    node walk with flush-on-graph-change pool accumulation.
// ---------------------------------------------------------------------------
__global__ void k_l2pool(const float* __restrict__ W2, const float* __restrict__ b2,
                         const int* __restrict__ batch) {
    __shared__ __half w2h[F1 * F2];       // 16 KB
    __shared__ float  cbuf[16 * F2];      // 8 KB (one m-tile of C)
    __shared__ float  dv_s[NPB];
    __shared__ int    bt_s[NPB];
    int tid  = threadIdx.x;               // 128
    int warp = tid >> 5;
    for (int i = tid; i < F1 * F2; i += 128) w2h[i] = __float2half(W2[i]);
    int base = blockIdx.x * NPB;
    if (tid < NPB) {
        dv_s[tid] = d_dinv[base + tid];
        bt_s[tid] = batch[base + tid];
    }
    float bb = b2[tid];
    __syncthreads();

    // Hoist B fragments: 4 k-steps x 2 n-tiles per warp
    wmma::fragment<wmma::matrix_b, 16, 16, 16, __half, wmma::row_major> bf[4][2];
#pragma unroll
    for (int k = 0; k < 4; k++)
#pragma unroll
        for (int nf = 0; nf < 2; nf++)
            wmma::load_matrix_sync(bf[k][nf], &w2h[(k * 16) * F2 + warp * 32 + nf * 16], F2);

    const __half* A = reinterpret_cast<const __half*>(d_acc1h);
    float pacc = 0.f;
    int cgid = bt_s[0];
    for (int mt = 0; mt < NPB / 16; mt++) {
        wmma::fragment<wmma::accumulator, 16, 16, 16, float> cf[2];
        wmma::fill_fragment(cf[0], 0.f);
        wmma::fill_fragment(cf[1], 0.f);
        const __half* Am = A + (base + mt * 16) * F1;
#pragma unroll
        for (int k = 0; k < 4; k++) {
            wmma::fragment<wmma::matrix_a, 16, 16, 16, __half, wmma::row_major> af;
            wmma::load_matrix_sync(af, Am + k * 16, F1);
            wmma::mma_sync(cf[0], af, bf[k][0], cf[0]);
            wmma::mma_sync(cf[1], af, bf[k][1], cf[1]);
        }
        wmma::store_matrix_sync(&cbuf[warp * 32 + 0],  cf[0], F2, wmma::mem_row_major);
        wmma::store_matrix_sync(&cbuf[warp * 32 + 16], cf[1], F2, wmma::mem_row_major);
        __syncthreads();
        // epilogue: 16 nodes in order, tid = output feature
#pragma unroll 4
        for (int t = 0; t < 16; t++) {
            int nl = mt * 16 + t;
            int gid = bt_s[nl];
            if (gid != cgid) {
                atomicAdd(&d_pool[cgid * F2 + tid], pacc);
                pacc = 0.f;
                cgid = gid;
            }
            pacc += relu(dv_s[nl] * cbuf[t * F2 + tid] + bb);
        }
        __syncthreads();
    }
    atomicAdd(&d_pool[cgid * F2 + tid], pacc);
}

// ---------------------------------------------------------------------------
// 8) out[g] = (pool[g]/max(cnt,1)) @ Wfc + bfc      [1000, 2]
// ---------------------------------------------------------------------------
__global__ void k_fc(const float* __restrict__ Wfc, const float* __restrict__ bfc,
                     float* __restrict__ out) {
    int i = blockIdx.x * blockDim.x + threadIdx.x;
    if (i >= NG * 2) return;
    int g = i >> 1;
    int o = i & 1;
    float cnt = d_cntf[g];
    float inv = 1.f / (cnt > 1.f ? cnt : 1.f);
    float a = 0.f;
#pragma unroll 8
    for (int k = 0; k < F2; k++) a += d_pool[g * F2 + k] * Wfc[k * 2 + o];
    out[i] = a * inv + bfc[o];
}

// ---------------------------------------------------------------------------
extern "C" void kernel_launch(void* const* d_in, const int* in_sizes, int n_in,
                              void* d_out, int out_size) {
    const float* x   = (const float*)d_in[0];
    const int*   ei  = (const int*)d_in[1];   // int32 (JAX x64 disabled)
    const int*   bat = (const int*)d_in[2];   // int32
    const float* W1  = (const float*)d_in[3];
    const float* b1  = (const float*)d_in[4];
    const float* W2  = (const float*)d_in[5];
    const float* b2  = (const float*)d_in[6];
    const float* Wfc = (const float*)d_in[7];
    const float* bfc = (const float*)d_in[8];
    float*       out = (float*)d_out;

    k_init   <<<(NG * F2 + 255) / 256, 256>>>();
    k_hist   <<<(NE / 4 + 255) / 256, 256>>>(ei);
    k_scan1  <<<NB_SCAN, SCAN_B>>>(x, bat);
    k_scan3  <<<1, 128>>>();
    k_fill   <<<(NE / 4 + 255) / 256, 256>>>(ei);
    k_pull0l1<<<(NN + 255) / 256, 256>>>(W1, b1);
    k_pull1  <<<(NN * 32 + 255) / 256, 256>>>();
    k_l2pool <<<NN / NPB, 128>>>(W2, b2, bat);
    k_fc     <<<(NG * 2 + 255) / 256, 256>>>(Wfc, bfc, out);
}